// round 2
// baseline (speedup 1.0000x reference)
#include <cuda_runtime.h>
#include <cstdint>
#include <math.h>

#define JAX_PARTITIONABLE 1   // flip to 0 (legacy threefry counters) if rel_err explodes

#define NB 2
#define NC 64
#define NN 144
#define NM 145
#define NL 800

// ---------------- scratch (device globals; no allocation) -------------------
__device__ float g_pos[NB*NN*NC];
__device__ float g_pa[NL];
__device__ float g_nodes_cg[NB*NM*NC];
__device__ float g_nodes_id[NB*NM*NC];
__device__ float g_pi [NB*NN*NL];
__device__ float g_pjp[NB*NN*NL];
__device__ float g_xl_cg[NB*NM*NL];
__device__ float g_xr_cg[NB*NM*NL];
__device__ float g_xl_id[NB*NM*NL];
__device__ float g_xr_id[NB*NM*NL];
__device__ float g_cg[NB*NN*NN];
__device__ float g_e[NB*NM*NM];
__device__ float g_alpha[NB*NM*NM];
__device__ float g_agg_cg[NB*NM*NL];
__device__ float g_agg_id[NB*NM*NL];
__device__ float g_y_cg[NB*NM*NC];
__device__ float g_y_id[NB*NM*NC];
__device__ float g_loss1, g_loss2;

// ---------------- threefry2x32 (JAX-exact) ----------------------------------
__host__ __device__ __forceinline__ void tf2x32(uint32_t k0, uint32_t k1,
                                                uint32_t x0, uint32_t x1,
                                                uint32_t &o0, uint32_t &o1) {
  uint32_t k2 = k0 ^ k1 ^ 0x1BD11BDAu;
  x0 += k0; x1 += k1;
#define TFR(r) { x0 += x1; x1 = (x1 << (r)) | (x1 >> (32 - (r))); x1 ^= x0; }
  TFR(13) TFR(15) TFR(26) TFR(6)
  x0 += k1; x1 += k2 + 1u;
  TFR(17) TFR(29) TFR(16) TFR(24)
  x0 += k2; x1 += k0 + 2u;
  TFR(13) TFR(15) TFR(26) TFR(6)
  x0 += k0; x1 += k1 + 3u;
  TFR(17) TFR(29) TFR(16) TFR(24)
  x0 += k1; x1 += k2 + 4u;
  TFR(13) TFR(15) TFR(26) TFR(6)
  x0 += k2; x1 += k0 + 5u;
#undef TFR
  o0 = x0; o1 = x1;
}

__device__ __forceinline__ uint32_t jx_bits(uint32_t k0, uint32_t k1,
                                            uint32_t f, uint32_t half) {
#if JAX_PARTITIONABLE
  uint32_t o0, o1; tf2x32(k0, k1, 0u, f, o0, o1); return o0 ^ o1;
#else
  uint32_t o0, o1;
  if (f < half) { tf2x32(k0, k1, f, f + half, o0, o1); return o0; }
  else          { tf2x32(k0, k1, f - half, f, o0, o1); return o1; }
#endif
}

__device__ __forceinline__ float jx_u01(uint32_t bits) {
  return __uint_as_float((bits >> 9) | 0x3F800000u) - 1.0f;
}

__device__ __forceinline__ float jx_gumbel(uint32_t k0, uint32_t k1,
                                           uint32_t f, uint32_t half) {
  float u01 = jx_u01(jx_bits(k0, k1, f, half));
  const float tiny = 1.17549435e-38f;
  float u = fmaxf(tiny, u01 + tiny);
  return -logf(-logf(u));
}

__device__ __forceinline__ float jx_normal(uint32_t k0, uint32_t k1,
                                           uint32_t f, uint32_t half) {
  float u01 = jx_u01(jx_bits(k0, k1, f, half));
  const float lo = -0.99999994f;
  float u = fmaxf(lo, u01 * 2.0f + lo);
  return 1.41421356f * erfinvf(u);
}

// ---------------- K0: pos, pa, noisy nodes ----------------------------------
__global__ void k0_prep(const float* __restrict__ latent,
                        const float* __restrict__ a_dense_b,
                        const float* __restrict__ disc_w1,
                        const float* __restrict__ disc_b1,
                        uint32_t n10, uint32_t n11, uint32_t n20, uint32_t n21) {
  int tid = blockIdx.x * blockDim.x + threadIdx.x;
  if (tid == 0) { g_loss1 = 0.f; g_loss2 = 0.f; }
  const float t = -logf(10000.0f) / 64.0f;
  if (tid < NB*NN*NC) {
    int b = tid / (NN*NC), r = tid % (NN*NC);
    int n = r >> 6, c = r & 63;
    int h = n / 12, w = n % 12;
    float lat = latent[((b*NC + c)*12 + h)*12 + w];
    float dv = expf((float)(2*(c >> 1)) * t);
    float ang = (float)n * dv;
    float pe = (c & 1) ? cosf(ang) : sinf(ang);
    g_pos[tid] = lat + pe;
  } else if (tid < NB*NN*NC + NL) {
    int l = tid - NB*NN*NC;
    float s = disc_b1[l];
    #pragma unroll 8
    for (int c = 0; c < NC; c++) s += a_dense_b[c] * disc_w1[(2*NC + c)*NL + l];
    g_pa[l] = s;
  } else if (tid < NB*NN*NC + NL + 2*NB*NM*NC) {
    int q = tid - (NB*NN*NC + NL);
    int which = q / (NB*NM*NC);
    int f = q % (NB*NM*NC);
    int b = f / (NM*NC), r = f % (NM*NC);
    int m = r >> 6, c = r & 63;
    float base;
    if (m < NN) {
      int h = m / 12, w = m % 12;
      float lat = latent[((b*NC + c)*12 + h)*12 + w];
      float dv = expf((float)(2*(c >> 1)) * t);
      float ang = (float)m * dv;
      float pe = (c & 1) ? cosf(ang) : sinf(ang);
      base = lat + pe;
    } else {
      base = a_dense_b[c];
    }
    uint32_t k0 = which ? n20 : n10, k1 = which ? n21 : n11;
    float noise = jx_normal(k0, k1, (uint32_t)f, (uint32_t)(NB*NM*NC/2));
    (which ? g_nodes_id : g_nodes_cg)[f] = base + noise;
  }
}

// ---------------- K1: six (rows x 64) @ (64 x 800) GEMMs --------------------
__global__ void k1_gemm64(const float* __restrict__ disc_w1,
                          const float* __restrict__ gat_wl,
                          const float* __restrict__ gat_wr,
                          const float* __restrict__ gat_bl,
                          const float* __restrict__ gat_br) {
  __shared__ float As[32][65];
  __shared__ float Ws[64][33];
  const float *A, *W, *bias; float *C; int rows;
  switch (blockIdx.z) {
    case 0:  A = g_pos;      W = disc_w1;          bias = nullptr; C = g_pi;    rows = NB*NN; break;
    case 1:  A = g_pos;      W = disc_w1 + NC*NL;  bias = g_pa;    C = g_pjp;   rows = NB*NN; break;
    case 2:  A = g_nodes_cg; W = gat_wl;           bias = gat_bl;  C = g_xl_cg; rows = NB*NM; break;
    case 3:  A = g_nodes_cg; W = gat_wr;           bias = gat_br;  C = g_xr_cg; rows = NB*NM; break;
    case 4:  A = g_nodes_id; W = gat_wl;           bias = gat_bl;  C = g_xl_id; rows = NB*NM; break;
    default: A = g_nodes_id; W = gat_wr;           bias = gat_br;  C = g_xr_id; rows = NB*NM; break;
  }
  int r0 = blockIdx.x * 32, c0 = blockIdx.y * 32;
  if (r0 >= rows) return;
  int tid = threadIdx.x, ty = tid >> 4, tx = tid & 15;
  for (int idx = tid; idx < 2048; idx += 256) {
    int r = idx >> 6, c = idx & 63;
    As[r][c] = (r0 + r < rows) ? A[(r0 + r)*NC + c] : 0.f;
    int wr = idx >> 5, wc = idx & 31;
    Ws[wr][wc] = W[wr*NL + c0 + wc];
  }
  __syncthreads();
  float a00 = 0.f, a01 = 0.f, a10 = 0.f, a11 = 0.f;
  #pragma unroll
  for (int k = 0; k < 64; k++) {
    float x0 = As[2*ty][k], x1 = As[2*ty+1][k];
    float w0 = Ws[k][2*tx], w1 = Ws[k][2*tx+1];
    a00 += x0*w0; a01 += x0*w1; a10 += x1*w0; a11 += x1*w1;
  }
  int r = r0 + 2*ty, c = c0 + 2*tx;
  float b0 = bias ? bias[c] : 0.f, b1 = bias ? bias[c+1] : 0.f;
  if (r < rows)     { C[r*NL + c] = a00 + b0;       C[r*NL + c + 1] = a01 + b1; }
  if (r + 1 < rows) { C[(r+1)*NL + c] = a10 + b0;   C[(r+1)*NL + c + 1] = a11 + b1; }
}

// ---------------- K2: discriminator pairwise -> gumbel hard cg --------------
__global__ void k2_disc(const float* __restrict__ disc_w2,
                        const float* __restrict__ disc_b2,
                        uint32_t kg0, uint32_t kg1) {
  __shared__ float Ps[16][33], Qs[16][33], w2s[32];
  __shared__ float red[256];
  int b = blockIdx.z;
  int i0 = blockIdx.x * 16, j0 = blockIdx.y * 16;
  int tid = threadIdx.x, ty = tid >> 4, tx = tid & 15;
  const float* pi = g_pi  + b*NN*NL;
  const float* pj = g_pjp + b*NN*NL;
  float acc = 0.f;
  for (int l0 = 0; l0 < NL; l0 += 32) {
    for (int idx = tid; idx < 512; idx += 256) {
      int r = idx >> 5, k = idx & 31;
      Ps[r][k] = pi[(i0 + r)*NL + l0 + k];
      Qs[r][k] = pj[(j0 + r)*NL + l0 + k];
    }
    if (tid < 32) w2s[tid] = disc_w2[l0 + tid];
    __syncthreads();
    #pragma unroll
    for (int k = 0; k < 32; k++) {
      float t = Ps[ty][k] + Qs[tx][k];
      acc += w2s[k] * fmaxf(t, 0.01f * t);
    }
    __syncthreads();
  }
  int i = i0 + ty, j = j0 + tx;
  float z  = acc + disc_b2[0];
  float cf = 1.0f / (1.0f + expf(-z));
  float l1 = logf(cf), l0v = logf(1.0f - cf);
  uint32_t f = (uint32_t)(((b*NN + i)*NN + j) * 2);
  float gg0 = jx_gumbel(kg0, kg1, f,      (uint32_t)(NB*NN*NN));
  float gg1 = jx_gumbel(kg0, kg1, f + 1u, (uint32_t)(NB*NN*NN));
  float cgv = (l1 + gg1 > l0v + gg0) ? 1.0f : 0.0f;
  g_cg[(b*NN + i)*NN + j] = cgv;
  float d = (i == j) ? (1.0f - cgv) : cgv;
  red[tid] = d * d;
  __syncthreads();
  for (int s = 128; s > 0; s >>= 1) { if (tid < s) red[tid] += red[tid + s]; __syncthreads(); }
  if (tid == 0) atomicAdd(&g_loss1, red[0]);
}

// ---------------- K3: dense GAT logits for cg graph -------------------------
__global__ void k3_ecg(const float* __restrict__ gat_att) {
  __shared__ float Ls[16][33], Rs[16][33], atts[32];
  int b = blockIdx.z;
  int i0 = blockIdx.x * 16, j0 = blockIdx.y * 16;
  int tid = threadIdx.x, ty = tid >> 4, tx = tid & 15;
  const float* xl = g_xl_cg + b*NM*NL;
  const float* xr = g_xr_cg + b*NM*NL;
  float acc = 0.f;
  for (int l0 = 0; l0 < NL; l0 += 32) {
    for (int idx = tid; idx < 512; idx += 256) {
      int r = idx >> 5, k = idx & 31;
      Ls[r][k] = (i0 + r < NM) ? xl[(i0 + r)*NL + l0 + k] : 0.f;
      Rs[r][k] = (j0 + r < NM) ? xr[(j0 + r)*NL + l0 + k] : 0.f;
    }
    if (tid < 32) atts[tid] = gat_att[l0 + tid];
    __syncthreads();
    #pragma unroll
    for (int k = 0; k < 32; k++) {
      float t = Ls[ty][k] + Rs[tx][k];
      acc += atts[k] * fmaxf(t, 0.2f * t);
    }
    __syncthreads();
  }
  int i = i0 + ty, j = j0 + tx;
  if (i < NM && j < NM) {
    bool mask = (i == NN) || (j == NN) || (i == j) ||
                (g_cg[(b*NN + i)*NN + j] != 0.0f);
    g_e[(b*NM + i)*NM + j] = mask ? acc : -1e30f;
  }
}

// ---------------- K3.5: column softmax (axis=1 over i) ----------------------
__global__ void k35_softmax() {
  int warp = (blockIdx.x * blockDim.x + threadIdx.x) >> 5;
  int lane = threadIdx.x & 31;
  if (warp >= NB*NM) return;
  int b = warp / NM, j = warp % NM;
  const float* e = g_e + b*NM*NM;
  float m = -3.4e38f;
  for (int i = lane; i < NM; i += 32) m = fmaxf(m, e[i*NM + j]);
  for (int s = 16; s; s >>= 1) m = fmaxf(m, __shfl_xor_sync(0xffffffffu, m, s));
  float sum = 0.f;
  for (int i = lane; i < NM; i += 32) sum += expf(e[i*NM + j] - m);
  for (int s = 16; s; s >>= 1) sum += __shfl_xor_sync(0xffffffffu, sum, s);
  float inv = 1.0f / sum;
  float* a = g_alpha + b*NM*NM;
  for (int i = lane; i < NM; i += 32) a[i*NM + j] = expf(e[i*NM + j] - m) * inv;
}

// ---------------- K4: agg_cg[j,l] = relu(sum_i alpha[i,j]*xl[i,l]+bias) -----
__global__ void k4_aggcg(const float* __restrict__ gat_bias) {
  __shared__ float As[32][33];
  __shared__ float Xs[32][33];
  int b = blockIdx.z;
  int j0 = blockIdx.x * 32, l0 = blockIdx.y * 32;
  int tid = threadIdx.x, ty = tid >> 4, tx = tid & 15;
  const float* alpha = g_alpha + b*NM*NM;
  const float* xl = g_xl_cg + b*NM*NL;
  float a00 = 0.f, a01 = 0.f, a10 = 0.f, a11 = 0.f;
  for (int i0 = 0; i0 < NM; i0 += 32) {
    for (int idx = tid; idx < 1024; idx += 256) {
      int r = idx >> 5, c = idx & 31;
      As[r][c] = (i0 + r < NM && j0 + c < NM) ? alpha[(i0 + r)*NM + j0 + c] : 0.f;
      Xs[r][c] = (i0 + r < NM) ? xl[(i0 + r)*NL + l0 + c] : 0.f;
    }
    __syncthreads();
    #pragma unroll
    for (int k = 0; k < 32; k++) {
      float aj0 = As[k][2*ty], aj1 = As[k][2*ty+1];
      float x0 = Xs[k][2*tx], x1 = Xs[k][2*tx+1];
      a00 += aj0*x0; a01 += aj0*x1; a10 += aj1*x0; a11 += aj1*x1;
    }
    __syncthreads();
  }
  float* outp = g_agg_cg + b*NM*NL;
  int j = j0 + 2*ty, l = l0 + 2*tx;
  float bb0 = gat_bias[l], bb1 = gat_bias[l+1];
  if (j < NM)     { outp[j*NL + l] = fmaxf(a00 + bb0, 0.f);     outp[j*NL + l + 1] = fmaxf(a01 + bb1, 0.f); }
  if (j + 1 < NM) { outp[(j+1)*NL + l] = fmaxf(a10 + bb0, 0.f); outp[(j+1)*NL + l + 1] = fmaxf(a11 + bb1, 0.f); }
}

// ---------------- K5: identity-graph transitioner (sparse mask) -------------
__global__ void k5_id(const float* __restrict__ gat_att,
                      const float* __restrict__ gat_bias) {
  __shared__ float es[160];
  __shared__ float red[256];
  __shared__ float abuf[2];
  int b = blockIdx.x, j = blockIdx.y;
  int tid = threadIdx.x;
  const float* xl = g_xl_id + b*NM*NL;
  const float* xr = g_xr_id + b*NM*NL;
  float* outp = g_agg_id + b*NM*NL;
  if (j < NN) {
    float s1 = 0.f, s2 = 0.f;
    for (int l = tid; l < NL; l += 256) {
      float xrv = xr[j*NL + l];
      float a = gat_att[l];
      float t1 = xl[j*NL + l] + xrv;
      s1 += a * fmaxf(t1, 0.2f * t1);
      float t2 = xl[NN*NL + l] + xrv;
      s2 += a * fmaxf(t2, 0.2f * t2);
    }
    red[tid] = s1; __syncthreads();
    for (int s = 128; s; s >>= 1) { if (tid < s) red[tid] += red[tid + s]; __syncthreads(); }
    float e1 = red[0]; __syncthreads();
    red[tid] = s2; __syncthreads();
    for (int s = 128; s; s >>= 1) { if (tid < s) red[tid] += red[tid + s]; __syncthreads(); }
    float e2 = red[0];
    float m = fmaxf(e1, e2);
    float x1 = expf(e1 - m), x2 = expf(e2 - m);
    float inv = 1.0f / (x1 + x2);
    float al1 = x1 * inv, al2 = x2 * inv;
    for (int l = tid; l < NL; l += 256) {
      float v = al1 * xl[j*NL + l] + al2 * xl[NN*NL + l] + gat_bias[l];
      outp[j*NL + l] = fmaxf(v, 0.f);
    }
  } else {
    int wid = tid >> 5, lane = tid & 31;
    for (int i = wid; i < NM; i += 8) {
      float s = 0.f;
      for (int l = lane; l < NL; l += 32) {
        float t = xl[i*NL + l] + xr[NN*NL + l];
        s += gat_att[l] * fmaxf(t, 0.2f * t);
      }
      for (int sh = 16; sh; sh >>= 1) s += __shfl_xor_sync(0xffffffffu, s, sh);
      if (lane == 0) es[i] = s;
    }
    __syncthreads();
    if (tid == 0) {
      float m = -3.4e38f;
      for (int i = 0; i < NM; i++) m = fmaxf(m, es[i]);
      float sum = 0.f;
      for (int i = 0; i < NM; i++) sum += expf(es[i] - m);
      abuf[0] = m; abuf[1] = 1.0f / sum;
    }
    __syncthreads();
    float m = abuf[0], inv = abuf[1];
    for (int i = tid; i < NM; i += 256) es[i] = expf(es[i] - m) * inv;
    __syncthreads();
    for (int l = tid; l < NL; l += 256) {
      float acc = gat_bias[l];
      for (int i = 0; i < NM; i++) acc += es[i] * xl[i*NL + l];
      outp[NN*NL + l] = fmaxf(acc, 0.f);
    }
  }
}

// ---------------- K6: output projection (290 x 800) @ (800 x 64) ------------
__global__ void k6_proj(const float* __restrict__ out_w,
                        const float* __restrict__ out_b) {
  __shared__ float As[32][33], Ws[32][33];
  int g = blockIdx.z;
  const float* A = g ? g_agg_id : g_agg_cg;
  float* Y = g ? g_y_id : g_y_cg;
  int r0 = blockIdx.x * 32, c0 = blockIdx.y * 32;
  int tid = threadIdx.x, ty = tid >> 4, tx = tid & 15;
  float a00 = 0.f, a01 = 0.f, a10 = 0.f, a11 = 0.f;
  for (int k0 = 0; k0 < NL; k0 += 32) {
    for (int idx = tid; idx < 1024; idx += 256) {
      int r = idx >> 5, c = idx & 31;
      As[r][c] = (r0 + r < NB*NM) ? A[(r0 + r)*NL + k0 + c] : 0.f;
      Ws[r][c] = out_w[(k0 + r)*NC + c0 + c];
    }
    __syncthreads();
    #pragma unroll
    for (int k = 0; k < 32; k++) {
      float ar0 = As[2*ty][k], ar1 = As[2*ty+1][k];
      float w0 = Ws[k][2*tx], w1 = Ws[k][2*tx+1];
      a00 += ar0*w0; a01 += ar0*w1; a10 += ar1*w0; a11 += ar1*w1;
    }
    __syncthreads();
  }
  int r = r0 + 2*ty, c = c0 + 2*tx;
  if (r < NB*NM)     { Y[r*NC + c] = a00 + out_b[c];     Y[r*NC + c + 1] = a01 + out_b[c+1]; }
  if (r + 1 < NB*NM) { Y[(r+1)*NC + c] = a10 + out_b[c]; Y[(r+1)*NC + c + 1] = a11 + out_b[c+1]; }
}

// ---------------- K7: write latent_y + loss2 partials -----------------------
__global__ void k7_final(const float* __restrict__ latent, float* __restrict__ d_out) {
  __shared__ float red[256];
  int tid = threadIdx.x;
  int idx = blockIdx.x * 256 + tid;
  float lp = 0.f;
  if (idx < NB*NN*NC) {
    int b = idx / (NC*NN), r = idx % (NC*NN);
    int c = r / NN, n = r % NN;
    d_out[idx] = g_y_cg[(b*NM + n)*NC + c];
    float d = latent[idx] - g_y_id[(b*NM + n)*NC + c];
    lp = d * d;
  }
  red[tid] = lp; __syncthreads();
  for (int s = 128; s; s >>= 1) { if (tid < s) red[tid] += red[tid + s]; __syncthreads(); }
  if (tid == 0) atomicAdd(&g_loss2, red[0]);
}

// ---------------- K8: finalize scalar loss ----------------------------------
__global__ void k8_loss(float* __restrict__ d_out) {
  if (threadIdx.x == 0 && blockIdx.x == 0)
    d_out[NB*NN*NC] = g_loss1 / (float)(NB*NN*NN) + g_loss2 / (float)(NB*NN*NC);
}

// ---------------- launch ----------------------------------------------------
extern "C" void kernel_launch(void* const* d_in, const int* in_sizes, int n_in,
                              void* d_out, int out_size) {
  (void)in_sizes; (void)n_in; (void)out_size;
  const float* latent    = (const float*)d_in[0];
  const float* a_dense_b = (const float*)d_in[2];
  const float* disc_w1   = (const float*)d_in[3];
  const float* disc_b1   = (const float*)d_in[4];
  const float* disc_w2   = (const float*)d_in[5];
  const float* disc_b2   = (const float*)d_in[6];
  const float* gat_wl    = (const float*)d_in[7];
  const float* gat_bl    = (const float*)d_in[8];
  const float* gat_wr    = (const float*)d_in[9];
  const float* gat_br    = (const float*)d_in[10];
  const float* gat_att   = (const float*)d_in[11];
  const float* gat_bias  = (const float*)d_in[12];
  const float* out_w     = (const float*)d_in[13];
  const float* out_b     = (const float*)d_in[14];
  float* out = (float*)d_out;

  // subkeys of jax.random.split(jax.random.key(42), 3), computed host-side
  uint32_t kg0, kg1, n10, n11, n20, n21;
#if JAX_PARTITIONABLE
  uint32_t a, b;
  tf2x32(0u, 42u, 0u, 0u, a, b); kg0 = a; kg1 = b;
  tf2x32(0u, 42u, 0u, 1u, a, b); n10 = a; n11 = b;
  tf2x32(0u, 42u, 0u, 2u, a, b); n20 = a; n21 = b;
#else
  uint32_t e0, f0, e1, f1, e2, f2;
  tf2x32(0u, 42u, 0u, 3u, e0, f0);
  tf2x32(0u, 42u, 1u, 4u, e1, f1);
  tf2x32(0u, 42u, 2u, 5u, e2, f2);
  kg0 = e0; kg1 = e1; n10 = e2; n11 = f0; n20 = f1; n21 = f2;
#endif

  int k0_threads = NB*NN*NC + NL + 2*NB*NM*NC;
  k0_prep<<<(k0_threads + 255)/256, 256>>>(latent, a_dense_b, disc_w1, disc_b1,
                                           n10, n11, n20, n21);
  k1_gemm64<<<dim3(10, 25, 6), 256>>>(disc_w1, gat_wl, gat_wr, gat_bl, gat_br);
  k2_disc<<<dim3(9, 9, 2), 256>>>(disc_w2, disc_b2, kg0, kg1);
  k3_ecg<<<dim3(10, 10, 2), 256>>>(gat_att);
  k35_softmax<<<37, 256>>>();
  k4_aggcg<<<dim3(5, 25, 2), 256>>>(gat_bias);
  k5_id<<<dim3(NB, NM), 256>>>(gat_att, gat_bias);
  k6_proj<<<dim3(10, 2, 2), 256>>>(out_w, out_b);
  k7_final<<<72, 256>>>(latent, out);
  k8_loss<<<1, 1>>>(out);
}

// round 3
// speedup vs baseline: 1.2516x; 1.2516x over previous
#include <cuda_runtime.h>
#include <cstdint>
#include <math.h>

#define NB 2
#define NC 64
#define NN 144
#define NM 145
#define NL 800

// ---------------- scratch (device globals; no allocation) -------------------
__device__ float g_pos[NB*NN*NC];
__device__ float g_pa[NL];
__device__ float g_nodes_cg[NB*NM*NC];
__device__ float g_nodes_id[NB*NM*NC];
__device__ float g_pi [NB*NN*NL];
__device__ float g_pjp[NB*NN*NL];
__device__ float g_xl_cg[NB*NM*NL];
__device__ float g_xr_cg[NB*NM*NL];
__device__ float g_xl_id[NB*NM*NL];
__device__ float g_xr_id[NB*NM*NL];
__device__ float g_cg[NB*NN*NN];
__device__ float g_e[NB*NM*NM];          // accumulates c2g * sum_l att*|xl+xr|
__device__ float g_alpha[NB*NM*NM];
__device__ float g_agg_cg[NB*NM*NL];
__device__ float g_agg_id[NB*NM*NL];
__device__ float g_y_cg[NB*NM*NC];
__device__ float g_y_id[NB*NM*NC];
__device__ float g_zp[5*2*160*160];      // disc partial |.| sums (5 L-chunks)
__device__ float g_ud[NB*NN], g_vd[NB*NN];
__device__ float g_ug[NB*NM], g_vg[NB*NM];
__device__ float g_loss1, g_loss2;

// ---------------- threefry2x32 (JAX-exact, partitionable) -------------------
__host__ __device__ __forceinline__ void tf2x32(uint32_t k0, uint32_t k1,
                                                uint32_t x0, uint32_t x1,
                                                uint32_t &o0, uint32_t &o1) {
  uint32_t k2 = k0 ^ k1 ^ 0x1BD11BDAu;
  x0 += k0; x1 += k1;
#define TFR(r) { x0 += x1; x1 = (x1 << (r)) | (x1 >> (32 - (r))); x1 ^= x0; }
  TFR(13) TFR(15) TFR(26) TFR(6)
  x0 += k1; x1 += k2 + 1u;
  TFR(17) TFR(29) TFR(16) TFR(24)
  x0 += k2; x1 += k0 + 2u;
  TFR(13) TFR(15) TFR(26) TFR(6)
  x0 += k0; x1 += k1 + 3u;
  TFR(17) TFR(29) TFR(16) TFR(24)
  x0 += k1; x1 += k2 + 4u;
  TFR(13) TFR(15) TFR(26) TFR(6)
  x0 += k2; x1 += k0 + 5u;
#undef TFR
  o0 = x0; o1 = x1;
}

__device__ __forceinline__ uint32_t jx_bits(uint32_t k0, uint32_t k1, uint32_t f) {
  uint32_t o0, o1; tf2x32(k0, k1, 0u, f, o0, o1); return o0 ^ o1;
}
__device__ __forceinline__ float jx_u01(uint32_t bits) {
  return __uint_as_float((bits >> 9) | 0x3F800000u) - 1.0f;
}
__device__ __forceinline__ float jx_gumbel(uint32_t k0, uint32_t k1, uint32_t f) {
  float u01 = jx_u01(jx_bits(k0, k1, f));
  const float tiny = 1.17549435e-38f;
  float u = fmaxf(tiny, u01 + tiny);
  return -logf(-logf(u));
}
__device__ __forceinline__ float jx_normal(uint32_t k0, uint32_t k1, uint32_t f) {
  float u01 = jx_u01(jx_bits(k0, k1, f));
  const float lo = -0.99999994f;
  float u = fmaxf(lo, u01 * 2.0f + lo);
  return 1.41421356f * erfinvf(u);
}

// ---------------- K0: pos, pa, noisy nodes, zero e/losses -------------------
__global__ void k0_prep(const float* __restrict__ latent,
                        const float* __restrict__ a_dense_b,
                        const float* __restrict__ disc_w1,
                        const float* __restrict__ disc_b1,
                        uint32_t n10, uint32_t n11, uint32_t n20, uint32_t n21) {
  int tid = blockIdx.x * blockDim.x + threadIdx.x;
  if (tid == 0) { g_loss1 = 0.f; g_loss2 = 0.f; }
  const float t = -logf(10000.0f) / 64.0f;
  const int R0 = NB*NN*NC;
  const int R1 = R0 + NL;
  const int R2 = R1 + 2*NB*NM*NC;
  const int R3 = R2 + NB*NM*NM;
  if (tid < R0) {
    int b = tid / (NN*NC), r = tid % (NN*NC);
    int n = r >> 6, c = r & 63;
    int h = n / 12, w = n % 12;
    float lat = latent[((b*NC + c)*12 + h)*12 + w];
    float dv = expf((float)(2*(c >> 1)) * t);
    float ang = (float)n * dv;
    float pe = (c & 1) ? cosf(ang) : sinf(ang);
    g_pos[tid] = lat + pe;
  } else if (tid < R1) {
    int l = tid - R0;
    float s = disc_b1[l];
    #pragma unroll 8
    for (int c = 0; c < NC; c++) s += a_dense_b[c] * disc_w1[(2*NC + c)*NL + l];
    g_pa[l] = s;
  } else if (tid < R2) {
    int q = tid - R1;
    int which = q / (NB*NM*NC);
    int f = q % (NB*NM*NC);
    int b = f / (NM*NC), r = f % (NM*NC);
    int m = r >> 6, c = r & 63;
    float base;
    if (m < NN) {
      int h = m / 12, w = m % 12;
      float lat = latent[((b*NC + c)*12 + h)*12 + w];
      float dv = expf((float)(2*(c >> 1)) * t);
      float ang = (float)m * dv;
      float pe = (c & 1) ? cosf(ang) : sinf(ang);
      base = lat + pe;
    } else {
      base = a_dense_b[c];
    }
    uint32_t k0 = which ? n20 : n10, k1 = which ? n21 : n11;
    float noise = jx_normal(k0, k1, (uint32_t)f);
    (which ? g_nodes_id : g_nodes_cg)[f] = base + noise;
  } else if (tid < R3) {
    g_e[tid - R2] = 0.f;
  }
}

// ---------------- K1: six (rows x 64) @ (64 x 800) GEMMs --------------------
__global__ void k1_gemm64(const float* __restrict__ disc_w1,
                          const float* __restrict__ gat_wl,
                          const float* __restrict__ gat_wr,
                          const float* __restrict__ gat_bl,
                          const float* __restrict__ gat_br) {
  __shared__ float As[32][65];
  __shared__ float Ws[64][33];
  const float *A, *W, *bias; float *C; int rows;
  switch (blockIdx.z) {
    case 0:  A = g_pos;      W = disc_w1;          bias = nullptr; C = g_pi;    rows = NB*NN; break;
    case 1:  A = g_pos;      W = disc_w1 + NC*NL;  bias = g_pa;    C = g_pjp;   rows = NB*NN; break;
    case 2:  A = g_nodes_cg; W = gat_wl;           bias = gat_bl;  C = g_xl_cg; rows = NB*NM; break;
    case 3:  A = g_nodes_cg; W = gat_wr;           bias = gat_br;  C = g_xr_cg; rows = NB*NM; break;
    case 4:  A = g_nodes_id; W = gat_wl;           bias = gat_bl;  C = g_xl_id; rows = NB*NM; break;
    default: A = g_nodes_id; W = gat_wr;           bias = gat_br;  C = g_xr_id; rows = NB*NM; break;
  }
  int r0 = blockIdx.x * 32, c0 = blockIdx.y * 32;
  if (r0 >= rows) return;
  int tid = threadIdx.x, ty = tid >> 4, tx = tid & 15;
  for (int idx = tid; idx < 2048; idx += 256) {
    int r = idx >> 6, c = idx & 63;
    As[r][c] = (r0 + r < rows) ? A[(r0 + r)*NC + c] : 0.f;
    int wr = idx >> 5, wc = idx & 31;
    Ws[wr][wc] = W[wr*NL + c0 + wc];
  }
  __syncthreads();
  float a00 = 0.f, a01 = 0.f, a10 = 0.f, a11 = 0.f;
  #pragma unroll
  for (int k = 0; k < 64; k++) {
    float x0 = As[2*ty][k], x1 = As[2*ty+1][k];
    float w0 = Ws[k][2*tx], w1 = Ws[k][2*tx+1];
    a00 += x0*w0; a01 += x0*w1; a10 += x1*w0; a11 += x1*w1;
  }
  int r = r0 + 2*ty, c = c0 + 2*tx;
  float b0 = bias ? bias[c] : 0.f, b1 = bias ? bias[c+1] : 0.f;
  if (r < rows)     { C[r*NL + c] = a00 + b0;       C[r*NL + c + 1] = a01 + b1; }
  if (r + 1 < rows) { C[(r+1)*NL + c] = a10 + b0;   C[(r+1)*NL + c + 1] = a11 + b1; }
}

// ---------------- KUV: separable leaky terms u_i, v_j -----------------------
__global__ void kUV(const float* __restrict__ disc_w2,
                    const float* __restrict__ gat_att) {
  int warp = (blockIdx.x * blockDim.x + threadIdx.x) >> 5;
  int lane = threadIdx.x & 31;
  const int T0 = NB*NN, T1 = 2*NB*NN, T2 = 2*NB*NN + NB*NM, T3 = 2*NB*NN + 2*NB*NM;
  if (warp >= T3) return;
  const float *src, *wv; float scale, *dst; int row;
  if (warp < T0)      { src = g_pi;    wv = disc_w2; scale = 0.505f; dst = g_ud; row = warp; }
  else if (warp < T1) { src = g_pjp;   wv = disc_w2; scale = 0.505f; dst = g_vd; row = warp - T0; }
  else if (warp < T2) { src = g_xl_cg; wv = gat_att; scale = 0.6f;   dst = g_ug; row = warp - T1; }
  else                { src = g_xr_cg; wv = gat_att; scale = 0.6f;   dst = g_vg; row = warp - T2; }
  float s = 0.f;
  for (int l = lane; l < NL; l += 32) s += wv[l] * src[row*NL + l];
  #pragma unroll
  for (int sh = 16; sh; sh >>= 1) s += __shfl_xor_sync(0xffffffffu, s, sh);
  if (lane == 0) dst[row] = scale * s;
}

// ---------------- K2a: disc |.| partial sums (deterministic chunks) ---------
__global__ void k2a_part(const float* __restrict__ disc_w2) {
  __shared__ float Pt[32][33], Qt[32][33], ws[32];
  int bz = blockIdx.z;               // b*5 + chunk
  int b = bz / 5, c = bz % 5;
  int i0 = blockIdx.x * 32, j0 = blockIdx.y * 32;
  int tid = threadIdx.x, ty = tid >> 4, tx = tid & 15;
  const float* pi = g_pi  + b*NN*NL;
  const float* pj = g_pjp + b*NN*NL;
  float a00 = 0.f, a01 = 0.f, a10 = 0.f, a11 = 0.f;
  for (int l0 = c*160; l0 < c*160 + 160; l0 += 32) {
    #pragma unroll
    for (int u = 0; u < 4; u++) {
      int idx = tid + u*256;
      int r = idx >> 5, k = idx & 31;
      Pt[k][r] = (i0 + r < NN) ? pi[(i0 + r)*NL + l0 + k] : 0.f;
      Qt[k][r] = (j0 + r < NN) ? pj[(j0 + r)*NL + l0 + k] : 0.f;
    }
    if (tid < 32) ws[tid] = disc_w2[l0 + tid];
    __syncthreads();
    #pragma unroll
    for (int k = 0; k < 32; k++) {
      float a = ws[k];
      float p0 = Pt[k][2*ty], p1 = Pt[k][2*ty+1];
      float q0 = Qt[k][2*tx], q1 = Qt[k][2*tx+1];
      a00 = fmaf(a, fabsf(p0 + q0), a00);
      a01 = fmaf(a, fabsf(p0 + q1), a01);
      a10 = fmaf(a, fabsf(p1 + q0), a10);
      a11 = fmaf(a, fabsf(p1 + q1), a11);
    }
    __syncthreads();
  }
  float* zp = g_zp + (c*2 + b)*160*160;
  int i = i0 + 2*ty, j = j0 + 2*tx;
  zp[i*160 + j]         = a00;
  zp[i*160 + j + 1]     = a01;
  zp[(i+1)*160 + j]     = a10;
  zp[(i+1)*160 + j + 1] = a11;
}

// ---------------- K2b: combine -> sigmoid -> gumbel hard cg + loss1 ---------
__global__ void k2b_decide(const float* __restrict__ disc_b2,
                           uint32_t kg0, uint32_t kg1) {
  __shared__ float red[256];
  int tid = threadIdx.x;
  int gidx = blockIdx.x * 256 + tid;
  float lp = 0.f;
  if (gidx < NB*NN*NN) {
    int b = gidx / (NN*NN), r = gidx % (NN*NN);
    int i = r / NN, j = r % NN;
    float S = 0.f;
    #pragma unroll
    for (int cc = 0; cc < 5; cc++) S += g_zp[((cc*2 + b)*160 + i)*160 + j];
    float z = 0.495f*S + g_ud[b*NN + i] + g_vd[b*NN + j] + disc_b2[0];
    float cf = 1.0f / (1.0f + expf(-z));
    float l1 = logf(cf), l0v = logf(1.0f - cf);
    uint32_t f = (uint32_t)(gidx * 2);
    float gg0 = jx_gumbel(kg0, kg1, f);
    float gg1 = jx_gumbel(kg0, kg1, f + 1u);
    float cgv = (l1 + gg1 > l0v + gg0) ? 1.0f : 0.0f;
    g_cg[gidx] = cgv;
    float d = (i == j) ? (1.0f - cgv) : cgv;
    lp = d * d;
  }
  red[tid] = lp; __syncthreads();
  for (int s = 128; s; s >>= 1) { if (tid < s) red[tid] += red[tid + s]; __syncthreads(); }
  if (tid == 0) atomicAdd(&g_loss1, red[0]);
}

// ---------------- K3a: GAT |.| pairwise sums (atomic over L-chunks) ---------
__global__ void k3a_egat(const float* __restrict__ gat_att) {
  __shared__ float Pt[32][33], Qt[32][33], ws[32];
  int bz = blockIdx.z;
  int b = bz / 5, c = bz % 5;
  int i0 = blockIdx.x * 32, j0 = blockIdx.y * 32;
  int tid = threadIdx.x, ty = tid >> 4, tx = tid & 15;
  const float* xl = g_xl_cg + b*NM*NL;
  const float* xr = g_xr_cg + b*NM*NL;
  float a00 = 0.f, a01 = 0.f, a10 = 0.f, a11 = 0.f;
  for (int l0 = c*160; l0 < c*160 + 160; l0 += 32) {
    #pragma unroll
    for (int u = 0; u < 4; u++) {
      int idx = tid + u*256;
      int r = idx >> 5, k = idx & 31;
      Pt[k][r] = (i0 + r < NM) ? xl[(i0 + r)*NL + l0 + k] : 0.f;
      Qt[k][r] = (j0 + r < NM) ? xr[(j0 + r)*NL + l0 + k] : 0.f;
    }
    if (tid < 32) ws[tid] = gat_att[l0 + tid];
    __syncthreads();
    #pragma unroll
    for (int k = 0; k < 32; k++) {
      float a = ws[k];
      float p0 = Pt[k][2*ty], p1 = Pt[k][2*ty+1];
      float q0 = Qt[k][2*tx], q1 = Qt[k][2*tx+1];
      a00 = fmaf(a, fabsf(p0 + q0), a00);
      a01 = fmaf(a, fabsf(p0 + q1), a01);
      a10 = fmaf(a, fabsf(p1 + q0), a10);
      a11 = fmaf(a, fabsf(p1 + q1), a11);
    }
    __syncthreads();
  }
  int i = i0 + 2*ty, j = j0 + 2*tx;
  float* e = g_e + b*NM*NM;
  if (i < NM) {
    if (j < NM)     atomicAdd(&e[i*NM + j],     0.4f*a00);
    if (j + 1 < NM) atomicAdd(&e[i*NM + j + 1], 0.4f*a01);
  }
  if (i + 1 < NM) {
    if (j < NM)     atomicAdd(&e[(i+1)*NM + j],     0.4f*a10);
    if (j + 1 < NM) atomicAdd(&e[(i+1)*NM + j + 1], 0.4f*a11);
  }
}

// ---------------- K3.5: mask + column softmax (axis=1 over i) ---------------
__global__ void k35_softmax() {
  int warp = (blockIdx.x * blockDim.x + threadIdx.x) >> 5;
  int lane = threadIdx.x & 31;
  if (warp >= NB*NM) return;
  int b = warp / NM, j = warp % NM;
  const float* e = g_e + b*NM*NM;
  float vgj = g_vg[b*NM + j];
  auto eval = [&](int i) -> float {
    float ev = g_ug[b*NM + i] + vgj + e[i*NM + j];
    bool mask = (i == NN) || (j == NN) || (i == j);
    if (!mask) mask = g_cg[(b*NN + i)*NN + j] != 0.0f;
    return mask ? ev : -1e30f;
  };
  float m = -3.4e38f;
  for (int i = lane; i < NM; i += 32) m = fmaxf(m, eval(i));
  #pragma unroll
  for (int s = 16; s; s >>= 1) m = fmaxf(m, __shfl_xor_sync(0xffffffffu, m, s));
  float sum = 0.f;
  for (int i = lane; i < NM; i += 32) sum += expf(eval(i) - m);
  #pragma unroll
  for (int s = 16; s; s >>= 1) sum += __shfl_xor_sync(0xffffffffu, sum, s);
  float inv = 1.0f / sum;
  float* a = g_alpha + b*NM*NM;
  for (int i = lane; i < NM; i += 32) a[i*NM + j] = expf(eval(i) - m) * inv;
}

// ---------------- K4: agg_cg[j,l] = relu(sum_i alpha[i,j]*xl[i,l]+bias) -----
__global__ void k4_aggcg(const float* __restrict__ gat_bias) {
  __shared__ float As[32][33];
  __shared__ float Xs[32][33];
  int b = blockIdx.z;
  int j0 = blockIdx.x * 32, l0 = blockIdx.y * 32;
  int tid = threadIdx.x, ty = tid >> 4, tx = tid & 15;
  const float* alpha = g_alpha + b*NM*NM;
  const float* xl = g_xl_cg + b*NM*NL;
  float a00 = 0.f, a01 = 0.f, a10 = 0.f, a11 = 0.f;
  for (int i0 = 0; i0 < NM; i0 += 32) {
    for (int idx = tid; idx < 1024; idx += 256) {
      int r = idx >> 5, c = idx & 31;
      As[r][c] = (i0 + r < NM && j0 + c < NM) ? alpha[(i0 + r)*NM + j0 + c] : 0.f;
      Xs[r][c] = (i0 + r < NM) ? xl[(i0 + r)*NL + l0 + c] : 0.f;
    }
    __syncthreads();
    #pragma unroll
    for (int k = 0; k < 32; k++) {
      float aj0 = As[k][2*ty], aj1 = As[k][2*ty+1];
      float x0 = Xs[k][2*tx], x1 = Xs[k][2*tx+1];
      a00 += aj0*x0; a01 += aj0*x1; a10 += aj1*x0; a11 += aj1*x1;
    }
    __syncthreads();
  }
  float* outp = g_agg_cg + b*NM*NL;
  int j = j0 + 2*ty, l = l0 + 2*tx;
  float bb0 = gat_bias[l], bb1 = gat_bias[l+1];
  if (j < NM)     { outp[j*NL + l] = fmaxf(a00 + bb0, 0.f);     outp[j*NL + l + 1] = fmaxf(a01 + bb1, 0.f); }
  if (j + 1 < NM) { outp[(j+1)*NL + l] = fmaxf(a10 + bb0, 0.f); outp[(j+1)*NL + l + 1] = fmaxf(a11 + bb1, 0.f); }
}

// ---------------- K5: identity-graph transitioner (sparse mask) -------------
__global__ void k5_id(const float* __restrict__ gat_att,
                      const float* __restrict__ gat_bias) {
  __shared__ float es[160];
  __shared__ float red[256];
  __shared__ float abuf[2];
  int b = blockIdx.x, j = blockIdx.y;
  int tid = threadIdx.x;
  const float* xl = g_xl_id + b*NM*NL;
  const float* xr = g_xr_id + b*NM*NL;
  float* outp = g_agg_id + b*NM*NL;
  if (j < NN) {
    float s1 = 0.f, s2 = 0.f;
    for (int l = tid; l < NL; l += 256) {
      float xrv = xr[j*NL + l];
      float a = gat_att[l];
      float t1 = xl[j*NL + l] + xrv;
      s1 += a * fmaxf(t1, 0.2f * t1);
      float t2 = xl[NN*NL + l] + xrv;
      s2 += a * fmaxf(t2, 0.2f * t2);
    }
    red[tid] = s1; __syncthreads();
    for (int s = 128; s; s >>= 1) { if (tid < s) red[tid] += red[tid + s]; __syncthreads(); }
    float e1 = red[0]; __syncthreads();
    red[tid] = s2; __syncthreads();
    for (int s = 128; s; s >>= 1) { if (tid < s) red[tid] += red[tid + s]; __syncthreads(); }
    float e2 = red[0];
    float m = fmaxf(e1, e2);
    float x1 = expf(e1 - m), x2 = expf(e2 - m);
    float inv = 1.0f / (x1 + x2);
    float al1 = x1 * inv, al2 = x2 * inv;
    for (int l = tid; l < NL; l += 256) {
      float v = al1 * xl[j*NL + l] + al2 * xl[NN*NL + l] + gat_bias[l];
      outp[j*NL + l] = fmaxf(v, 0.f);
    }
  } else {
    int wid = tid >> 5, lane = tid & 31;
    for (int i = wid; i < NM; i += 8) {
      float s = 0.f;
      for (int l = lane; l < NL; l += 32) {
        float t = xl[i*NL + l] + xr[NN*NL + l];
        s += gat_att[l] * fmaxf(t, 0.2f * t);
      }
      for (int sh = 16; sh; sh >>= 1) s += __shfl_xor_sync(0xffffffffu, s, sh);
      if (lane == 0) es[i] = s;
    }
    __syncthreads();
    if (tid == 0) {
      float m = -3.4e38f;
      for (int i = 0; i < NM; i++) m = fmaxf(m, es[i]);
      float sum = 0.f;
      for (int i = 0; i < NM; i++) sum += expf(es[i] - m);
      abuf[0] = m; abuf[1] = 1.0f / sum;
    }
    __syncthreads();
    float m = abuf[0], inv = abuf[1];
    for (int i = tid; i < NM; i += 256) es[i] = expf(es[i] - m) * inv;
    __syncthreads();
    for (int l = tid; l < NL; l += 256) {
      float acc = gat_bias[l];
      for (int i = 0; i < NM; i++) acc += es[i] * xl[i*NL + l];
      outp[NN*NL + l] = fmaxf(acc, 0.f);
    }
  }
}

// ---------------- K6: output projection (290 x 800) @ (800 x 64) ------------
__global__ void k6_proj(const float* __restrict__ out_w,
                        const float* __restrict__ out_b) {
  __shared__ float As[32][33], Ws[32][33];
  int g = blockIdx.z;
  const float* A = g ? g_agg_id : g_agg_cg;
  float* Y = g ? g_y_id : g_y_cg;
  int r0 = blockIdx.x * 32, c0 = blockIdx.y * 32;
  int tid = threadIdx.x, ty = tid >> 4, tx = tid & 15;
  float a00 = 0.f, a01 = 0.f, a10 = 0.f, a11 = 0.f;
  for (int k0 = 0; k0 < NL; k0 += 32) {
    for (int idx = tid; idx < 1024; idx += 256) {
      int r = idx >> 5, c = idx & 31;
      As[r][c] = (r0 + r < NB*NM) ? A[(r0 + r)*NL + k0 + c] : 0.f;
      Ws[r][c] = out_w[(k0 + r)*NC + c0 + c];
    }
    __syncthreads();
    #pragma unroll
    for (int k = 0; k < 32; k++) {
      float ar0 = As[2*ty][k], ar1 = As[2*ty+1][k];
      float w0 = Ws[k][2*tx], w1 = Ws[k][2*tx+1];
      a00 += ar0*w0; a01 += ar0*w1; a10 += ar1*w0; a11 += ar1*w1;
    }
    __syncthreads();
  }
  int r = r0 + 2*ty, c = c0 + 2*tx;
  if (r < NB*NM)     { Y[r*NC + c] = a00 + out_b[c];     Y[r*NC + c + 1] = a01 + out_b[c+1]; }
  if (r + 1 < NB*NM) { Y[(r+1)*NC + c] = a10 + out_b[c]; Y[(r+1)*NC + c + 1] = a11 + out_b[c+1]; }
}

// ---------------- K7: write latent_y + loss2 partials -----------------------
__global__ void k7_final(const float* __restrict__ latent, float* __restrict__ d_out) {
  __shared__ float red[256];
  int tid = threadIdx.x;
  int idx = blockIdx.x * 256 + tid;
  float lp = 0.f;
  if (idx < NB*NN*NC) {
    int b = idx / (NC*NN), r = idx % (NC*NN);
    int c = r / NN, n = r % NN;
    d_out[idx] = g_y_cg[(b*NM + n)*NC + c];
    float d = latent[idx] - g_y_id[(b*NM + n)*NC + c];
    lp = d * d;
  }
  red[tid] = lp; __syncthreads();
  for (int s = 128; s; s >>= 1) { if (tid < s) red[tid] += red[tid + s]; __syncthreads(); }
  if (tid == 0) atomicAdd(&g_loss2, red[0]);
}

// ---------------- K8: finalize scalar loss ----------------------------------
__global__ void k8_loss(float* __restrict__ d_out) {
  if (threadIdx.x == 0 && blockIdx.x == 0)
    d_out[NB*NN*NC] = g_loss1 / (float)(NB*NN*NN) + g_loss2 / (float)(NB*NN*NC);
}

// ---------------- launch ----------------------------------------------------
extern "C" void kernel_launch(void* const* d_in, const int* in_sizes, int n_in,
                              void* d_out, int out_size) {
  (void)in_sizes; (void)n_in; (void)out_size;
  const float* latent    = (const float*)d_in[0];
  const float* a_dense_b = (const float*)d_in[2];
  const float* disc_w1   = (const float*)d_in[3];
  const float* disc_b1   = (const float*)d_in[4];
  const float* disc_w2   = (const float*)d_in[5];
  const float* disc_b2   = (const float*)d_in[6];
  const float* gat_wl    = (const float*)d_in[7];
  const float* gat_bl    = (const float*)d_in[8];
  const float* gat_wr    = (const float*)d_in[9];
  const float* gat_br    = (const float*)d_in[10];
  const float* gat_att   = (const float*)d_in[11];
  const float* gat_bias  = (const float*)d_in[12];
  const float* out_w     = (const float*)d_in[13];
  const float* out_b     = (const float*)d_in[14];
  float* out = (float*)d_out;

  // subkeys of jax.random.split(jax.random.key(42), 3)
  uint32_t kg0, kg1, n10, n11, n20, n21, a, b;
  tf2x32(0u, 42u, 0u, 0u, a, b); kg0 = a; kg1 = b;
  tf2x32(0u, 42u, 0u, 1u, a, b); n10 = a; n11 = b;
  tf2x32(0u, 42u, 0u, 2u, a, b); n20 = a; n21 = b;

  int k0_threads = NB*NN*NC + NL + 2*NB*NM*NC + NB*NM*NM;
  k0_prep<<<(k0_threads + 255)/256, 256>>>(latent, a_dense_b, disc_w1, disc_b1,
                                           n10, n11, n20, n21);
  k1_gemm64<<<dim3(10, 25, 6), 256>>>(disc_w1, gat_wl, gat_wr, gat_bl, gat_br);
  kUV<<<145, 256>>>(disc_w2, gat_att);
  k2a_part<<<dim3(5, 5, 10), 256>>>(disc_w2);
  k2b_decide<<<162, 256>>>(disc_b2, kg0, kg1);
  k3a_egat<<<dim3(5, 5, 10), 256>>>(gat_att);
  k35_softmax<<<37, 256>>>();
  k4_aggcg<<<dim3(5, 25, 2), 256>>>(gat_bias);
  k5_id<<<dim3(NB, NM), 256>>>(gat_att, gat_bias);
  k6_proj<<<dim3(10, 2, 2), 256>>>(out_w, out_b);
  k7_final<<<72, 256>>>(latent, out);
  k8_loss<<<1, 1>>>(out);
}

// round 5
// speedup vs baseline: 1.4819x; 1.1839x over previous
#include <cuda_runtime.h>
#include <cstdint>
#include <math.h>

#define NB 2
#define NC 64
#define NN 144
#define NM 145
#define NL 800

// ---------------- scratch (device globals; no allocation) -------------------
__device__ float g_pos[NB*NN*NC];
__device__ float g_pa[NL];
__device__ float g_nodes_cg[NB*NM*NC];
__device__ float g_nodes_id[NB*NM*NC];
__device__ float g_pi [NB*NN*NL];
__device__ float g_pjp[NB*NN*NL];
__device__ float g_xl_cg[NB*NM*NL];
__device__ float g_xr_cg[NB*NM*NL];
__device__ float g_xl_id[NB*NM*NL];
__device__ float g_xr_id[NB*NM*NL];
__device__ float g_cg[NB*NN*NN];
__device__ float g_e[NB*NM*NM];          // 0.4 * sum_l att*|xl+xr| (atomics)
__device__ float g_alphaT[NB*NM*NM];     // alpha transposed: [j][i]
__device__ float g_agg_cg[NB*NM*NL];
__device__ float g_agg_id[NB*NM*NL];
__device__ float g_y_cg[NB*NM*NC];
__device__ float g_y_id[NB*NM*NC];
__device__ float g_zp[5*2*160*160];      // disc partial |.| sums (5 L-chunks)
__device__ float g_ud[NB*NN], g_vd[NB*NN];   // raw dots (unscaled)
__device__ float g_ug[NB*NM], g_vg[NB*NM];
__device__ float g_loss1, g_loss2;
__device__ unsigned int g_cnt7;

// ---------------- threefry2x32 (JAX-exact, partitionable) -------------------
__host__ __device__ __forceinline__ void tf2x32(uint32_t k0, uint32_t k1,
                                                uint32_t x0, uint32_t x1,
                                                uint32_t &o0, uint32_t &o1) {
  uint32_t k2 = k0 ^ k1 ^ 0x1BD11BDAu;
  x0 += k0; x1 += k1;
#define TFR(r) { x0 += x1; x1 = (x1 << (r)) | (x1 >> (32 - (r))); x1 ^= x0; }
  TFR(13) TFR(15) TFR(26) TFR(6)
  x0 += k1; x1 += k2 + 1u;
  TFR(17) TFR(29) TFR(16) TFR(24)
  x0 += k2; x1 += k0 + 2u;
  TFR(13) TFR(15) TFR(26) TFR(6)
  x0 += k0; x1 += k1 + 3u;
  TFR(17) TFR(29) TFR(16) TFR(24)
  x0 += k1; x1 += k2 + 4u;
  TFR(13) TFR(15) TFR(26) TFR(6)
  x0 += k2; x1 += k0 + 5u;
#undef TFR
  o0 = x0; o1 = x1;
}

__device__ __forceinline__ uint32_t jx_bits(uint32_t k0, uint32_t k1, uint32_t f) {
  uint32_t o0, o1; tf2x32(k0, k1, 0u, f, o0, o1); return o0 ^ o1;
}
__device__ __forceinline__ float jx_u01(uint32_t bits) {
  return __uint_as_float((bits >> 9) | 0x3F800000u) - 1.0f;
}
__device__ __forceinline__ float jx_gumbel(uint32_t k0, uint32_t k1, uint32_t f) {
  float u01 = jx_u01(jx_bits(k0, k1, f));
  const float tiny = 1.17549435e-38f;
  float u = fmaxf(tiny, u01 + tiny);
  return -logf(-logf(u));
}
__device__ __forceinline__ float jx_normal(uint32_t k0, uint32_t k1, uint32_t f) {
  float u01 = jx_u01(jx_bits(k0, k1, f));
  const float lo = -0.99999994f;
  float u = fmaxf(lo, u01 * 2.0f + lo);
  return 1.41421356f * erfinvf(u);
}

// ---------------- K0: pos, pa, noisy nodes, zero accumulators ---------------
__global__ void k0_prep(const float* __restrict__ latent,
                        const float* __restrict__ a_dense_b,
                        const float* __restrict__ disc_w1,
                        const float* __restrict__ disc_b1,
                        uint32_t n10, uint32_t n11, uint32_t n20, uint32_t n21) {
  int tid = blockIdx.x * blockDim.x + threadIdx.x;
  if (tid == 0) { g_loss1 = 0.f; g_loss2 = 0.f; g_cnt7 = 0u; }
  const float t = -logf(10000.0f) / 64.0f;
  const int R0 = NB*NN*NC;
  const int R1 = R0 + NL;
  const int R2 = R1 + 2*NB*NM*NC;
  const int R3 = R2 + NB*NM*NM;
  const int R4 = R3 + 2*NB*NN + 2*NB*NM;
  if (tid < R0) {
    int b = tid / (NN*NC), r = tid % (NN*NC);
    int n = r >> 6, c = r & 63;
    int h = n / 12, w = n % 12;
    float lat = latent[((b*NC + c)*12 + h)*12 + w];
    float dv = expf((float)(2*(c >> 1)) * t);
    float ang = (float)n * dv;
    float pe = (c & 1) ? cosf(ang) : sinf(ang);
    g_pos[tid] = lat + pe;
  } else if (tid < R1) {
    int l = tid - R0;
    float s = disc_b1[l];
    #pragma unroll 8
    for (int c = 0; c < NC; c++) s += a_dense_b[c] * disc_w1[(2*NC + c)*NL + l];
    g_pa[l] = s;
  } else if (tid < R2) {
    int q = tid - R1;
    int which = q / (NB*NM*NC);
    int f = q % (NB*NM*NC);
    int b = f / (NM*NC), r = f % (NM*NC);
    int m = r >> 6, c = r & 63;
    float base;
    if (m < NN) {
      int h = m / 12, w = m % 12;
      float lat = latent[((b*NC + c)*12 + h)*12 + w];
      float dv = expf((float)(2*(c >> 1)) * t);
      float ang = (float)m * dv;
      float pe = (c & 1) ? cosf(ang) : sinf(ang);
      base = lat + pe;
    } else {
      base = a_dense_b[c];
    }
    uint32_t k0 = which ? n20 : n10, k1 = which ? n21 : n11;
    float noise = jx_normal(k0, k1, (uint32_t)f);
    (which ? g_nodes_id : g_nodes_cg)[f] = base + noise;
  } else if (tid < R3) {
    g_e[tid - R2] = 0.f;
  } else if (tid < R4) {
    int q = tid - R3;
    if (q < NB*NN) g_ud[q] = 0.f;
    else if (q < 2*NB*NN) g_vd[q - NB*NN] = 0.f;
    else if (q < 2*NB*NN + NB*NM) g_ug[q - 2*NB*NN] = 0.f;
    else g_vg[q - 2*NB*NN - NB*NM] = 0.f;
  }
}

// ---------------- K1: six (rows x 64)@(64 x 800) GEMMs + fused u/v ----------
__global__ void k1_gemm64(const float* __restrict__ disc_w1,
                          const float* __restrict__ gat_wl,
                          const float* __restrict__ gat_wr,
                          const float* __restrict__ gat_bl,
                          const float* __restrict__ gat_br,
                          const float* __restrict__ disc_w2,
                          const float* __restrict__ gat_att) {
  __shared__ __align__(16) float Ast[64][34];   // A transposed: [k][row]
  __shared__ __align__(16) float Ws[64][34];    // W: [k][col]
  const float *A, *W, *bias; float *C; int rows;
  const float *uvw = nullptr; float *uvdst = nullptr;
  switch (blockIdx.z) {
    case 0:  A = g_pos;      W = disc_w1;          bias = nullptr; C = g_pi;    rows = NB*NN;
             uvw = disc_w2; uvdst = g_ud; break;
    case 1:  A = g_pos;      W = disc_w1 + NC*NL;  bias = g_pa;    C = g_pjp;   rows = NB*NN;
             uvw = disc_w2; uvdst = g_vd; break;
    case 2:  A = g_nodes_cg; W = gat_wl;           bias = gat_bl;  C = g_xl_cg; rows = NB*NM;
             uvw = gat_att; uvdst = g_ug; break;
    case 3:  A = g_nodes_cg; W = gat_wr;           bias = gat_br;  C = g_xr_cg; rows = NB*NM;
             uvw = gat_att; uvdst = g_vg; break;
    case 4:  A = g_nodes_id; W = gat_wl;           bias = gat_bl;  C = g_xl_id; rows = NB*NM; break;
    default: A = g_nodes_id; W = gat_wr;           bias = gat_br;  C = g_xr_id; rows = NB*NM; break;
  }
  int r0 = blockIdx.x * 32, c0 = blockIdx.y * 32;
  if (r0 >= rows) return;
  int tid = threadIdx.x, ty = tid >> 4, tx = tid & 15;
  for (int idx = tid; idx < 2048; idx += 256) {
    int r = idx >> 6, c = idx & 63;
    Ast[c][r] = (r0 + r < rows) ? A[(r0 + r)*NC + c] : 0.f;
    int wr = idx >> 5, wc = idx & 31;
    Ws[wr][wc] = W[wr*NL + c0 + wc];
  }
  __syncthreads();
  float a00 = 0.f, a01 = 0.f, a10 = 0.f, a11 = 0.f;
  #pragma unroll
  for (int k = 0; k < 64; k++) {
    float2 x = *(const float2*)&Ast[k][2*ty];
    float2 w = *(const float2*)&Ws[k][2*tx];
    a00 = fmaf(x.x, w.x, a00); a01 = fmaf(x.x, w.y, a01);
    a10 = fmaf(x.y, w.x, a10); a11 = fmaf(x.y, w.y, a11);
  }
  int r = r0 + 2*ty, c = c0 + 2*tx;
  float b0 = bias ? bias[c] : 0.f, b1 = bias ? bias[c+1] : 0.f;
  float v00 = a00 + b0, v01 = a01 + b1, v10 = a10 + b0, v11 = a11 + b1;
  if (r < rows)     { C[r*NL + c] = v00;     C[r*NL + c + 1] = v01; }
  if (r + 1 < rows) { C[(r+1)*NL + c] = v10; C[(r+1)*NL + c + 1] = v11; }
  if (uvdst) {
    float w0 = uvw[c], w1 = uvw[c+1];
    float p0 = w0*v00 + w1*v01;          // contribution to row r
    float p1 = w0*v10 + w1*v11;          // row r+1
    #pragma unroll
    for (int sh = 8; sh; sh >>= 1) {
      p0 += __shfl_down_sync(0xffffffffu, p0, sh, 16);
      p1 += __shfl_down_sync(0xffffffffu, p1, sh, 16);
    }
    if (tx == 0) {
      if (r < rows)     atomicAdd(&uvdst[r], p0);
      if (r + 1 < rows) atomicAdd(&uvdst[r + 1], p1);
    }
  }
}

// ---------------- K235: merged pairwise (disc+gat) + id transitioner --------
__global__ void k235_mega(const float* __restrict__ disc_w2,
                          const float* __restrict__ gat_att,
                          const float* __restrict__ gat_bias) {
  __shared__ __align__(16) float sm[2*32*34 + 64];
  int bid = blockIdx.x;
  int tid = threadIdx.x;
  if (bid < 500) {
    // ---- pairwise |.| reduction ----
    int which = bid / 250;                 // 0 = disc, 1 = gat
    int z = bid % 250;
    int b = z / 125; z %= 125;
    int chunk = z / 25; int rz = z % 25;
    int i0 = (rz / 5) * 32, j0 = (rz % 5) * 32;
    float (*Pt)[34] = (float(*)[34])sm;
    float (*Qt)[34] = (float(*)[34])(sm + 32*34);
    float* ws = sm + 2*32*34;
    const float* pi; const float* pj; const float* wsg; int nrows;
    if (which == 0) { pi = g_pi  + b*NN*NL; pj = g_pjp + b*NN*NL; wsg = disc_w2; nrows = NN; }
    else            { pi = g_xl_cg + b*NM*NL; pj = g_xr_cg + b*NM*NL; wsg = gat_att; nrows = NM; }
    int ty = tid >> 4, tx = tid & 15;
    float a00 = 0.f, a01 = 0.f, a10 = 0.f, a11 = 0.f;
    for (int l0 = chunk*160; l0 < chunk*160 + 160; l0 += 32) {
      #pragma unroll
      for (int u = 0; u < 4; u++) {
        int idx = tid + u*256;
        int r = idx >> 5, k = idx & 31;
        Pt[k][r] = (i0 + r < nrows) ? pi[(i0 + r)*NL + l0 + k] : 0.f;
        Qt[k][r] = (j0 + r < nrows) ? pj[(j0 + r)*NL + l0 + k] : 0.f;
      }
      if (tid < 32) ws[tid] = wsg[l0 + tid];
      __syncthreads();
      #pragma unroll
      for (int k = 0; k < 32; k++) {
        float a = ws[k];
        float2 p = *(const float2*)&Pt[k][2*ty];
        float2 q = *(const float2*)&Qt[k][2*tx];
        a00 = fmaf(a, fabsf(p.x + q.x), a00);
        a01 = fmaf(a, fabsf(p.x + q.y), a01);
        a10 = fmaf(a, fabsf(p.y + q.x), a10);
        a11 = fmaf(a, fabsf(p.y + q.y), a11);
      }
      __syncthreads();
    }
    int i = i0 + 2*ty, j = j0 + 2*tx;
    if (which == 0) {
      float* zp = g_zp + (chunk*2 + b)*160*160;
      zp[i*160 + j]         = a00;
      zp[i*160 + j + 1]     = a01;
      zp[(i+1)*160 + j]     = a10;
      zp[(i+1)*160 + j + 1] = a11;
    } else {
      float* e = g_e + b*NM*NM;
      if (i < NM) {
        if (j < NM)     atomicAdd(&e[i*NM + j],     0.4f*a00);
        if (j + 1 < NM) atomicAdd(&e[i*NM + j + 1], 0.4f*a01);
      }
      if (i + 1 < NM) {
        if (j < NM)     atomicAdd(&e[(i+1)*NM + j],     0.4f*a10);
        if (j + 1 < NM) atomicAdd(&e[(i+1)*NM + j + 1], 0.4f*a11);
      }
    }
  } else {
    // ---- identity-graph transitioner ----
    int q = bid - 500;
    int b = q / NM, j = q % NM;
    float* es   = sm;          // 160
    float* red  = sm + 160;    // 256
    float* abuf = sm + 416;    // 2
    const float* xl = g_xl_id + b*NM*NL;
    const float* xr = g_xr_id + b*NM*NL;
    float* outp = g_agg_id + b*NM*NL;
    if (j < NN) {
      float s1 = 0.f, s2 = 0.f;
      for (int l = tid; l < NL; l += 256) {
        float xrv = xr[j*NL + l];
        float a = gat_att[l];
        float t1 = xl[j*NL + l] + xrv;
        s1 += a * fmaxf(t1, 0.2f * t1);
        float t2 = xl[NN*NL + l] + xrv;
        s2 += a * fmaxf(t2, 0.2f * t2);
      }
      red[tid] = s1; __syncthreads();
      for (int s = 128; s; s >>= 1) { if (tid < s) red[tid] += red[tid + s]; __syncthreads(); }
      float e1 = red[0]; __syncthreads();
      red[tid] = s2; __syncthreads();
      for (int s = 128; s; s >>= 1) { if (tid < s) red[tid] += red[tid + s]; __syncthreads(); }
      float e2 = red[0];
      float m = fmaxf(e1, e2);
      float x1 = expf(e1 - m), x2 = expf(e2 - m);
      float inv = 1.0f / (x1 + x2);
      float al1 = x1 * inv, al2 = x2 * inv;
      for (int l = tid; l < NL; l += 256) {
        float v = al1 * xl[j*NL + l] + al2 * xl[NN*NL + l] + gat_bias[l];
        outp[j*NL + l] = fmaxf(v, 0.f);
      }
    } else {
      int wid = tid >> 5, lane = tid & 31;
      for (int i = wid; i < NM; i += 8) {
        float s = 0.f;
        for (int l = lane; l < NL; l += 32) {
          float t = xl[i*NL + l] + xr[NN*NL + l];
          s += gat_att[l] * fmaxf(t, 0.2f * t);
        }
        for (int sh = 16; sh; sh >>= 1) s += __shfl_xor_sync(0xffffffffu, s, sh);
        if (lane == 0) es[i] = s;
      }
      __syncthreads();
      if (tid == 0) {
        float m = -3.4e38f;
        for (int i = 0; i < NM; i++) m = fmaxf(m, es[i]);
        float sum = 0.f;
        for (int i = 0; i < NM; i++) sum += expf(es[i] - m);
        abuf[0] = m; abuf[1] = 1.0f / sum;
      }
      __syncthreads();
      float m = abuf[0], inv = abuf[1];
      for (int i = tid; i < NM; i += 256) es[i] = expf(es[i] - m) * inv;
      __syncthreads();
      for (int l = tid; l < NL; l += 256) {
        float acc = gat_bias[l];
        for (int i = 0; i < NM; i++) acc += es[i] * xl[i*NL + l];
        outp[NN*NL + l] = fmaxf(acc, 0.f);
      }
    }
  }
}

// ---------------- K2b: combine -> sigmoid -> gumbel hard cg + loss1 ---------
__global__ void k2b_decide(const float* __restrict__ disc_b2,
                           uint32_t kg0, uint32_t kg1) {
  __shared__ float red[256];
  int tid = threadIdx.x;
  int gidx = blockIdx.x * 256 + tid;
  float lp = 0.f;
  if (gidx < NB*NN*NN) {
    int b = gidx / (NN*NN), r = gidx % (NN*NN);
    int i = r / NN, j = r % NN;
    float S = 0.f;
    #pragma unroll
    for (int cc = 0; cc < 5; cc++) S += g_zp[((cc*2 + b)*160 + i)*160 + j];
    float z = 0.495f*S + 0.505f*(g_ud[b*NN + i] + g_vd[b*NN + j]) + disc_b2[0];
    float cf = 1.0f / (1.0f + expf(-z));
    float l1 = logf(cf), l0v = logf(1.0f - cf);
    uint32_t f = (uint32_t)(gidx * 2);
    float gg0 = jx_gumbel(kg0, kg1, f);
    float gg1 = jx_gumbel(kg0, kg1, f + 1u);
    float cgv = (l1 + gg1 > l0v + gg0) ? 1.0f : 0.0f;
    g_cg[gidx] = cgv;
    float d = (i == j) ? (1.0f - cgv) : cgv;
    lp = d * d;
  }
  red[tid] = lp; __syncthreads();
  for (int s = 128; s; s >>= 1) { if (tid < s) red[tid] += red[tid + s]; __syncthreads(); }
  if (tid == 0) atomicAdd(&g_loss1, red[0]);
}

// ---------------- K35: mask + column softmax, single pass -------------------
__global__ void k35_softmax() {
  int warp = (blockIdx.x * blockDim.x + threadIdx.x) >> 5;
  int lane = threadIdx.x & 31;
  if (warp >= NB*NM) return;
  int b = warp / NM, j = warp % NM;
  const float* e = g_e + b*NM*NM;
  float vgj = g_vg[b*NM + j];
  float ev[5];
  #pragma unroll
  for (int t = 0; t < 5; t++) {
    int i = lane + 32*t;
    float v = -3.4e38f;
    if (i < NM) {
      bool mask = (i == NN) || (j == NN) || (i == j);
      if (!mask) mask = g_cg[(b*NN + i)*NN + j] != 0.0f;
      v = mask ? (0.6f*(g_ug[b*NM + i] + vgj) + e[i*NM + j]) : -1e30f;
    }
    ev[t] = v;
  }
  float m = -3.4e38f;
  #pragma unroll
  for (int t = 0; t < 5; t++) m = fmaxf(m, ev[t]);
  #pragma unroll
  for (int s = 16; s; s >>= 1) m = fmaxf(m, __shfl_xor_sync(0xffffffffu, m, s));
  float sum = 0.f;
  #pragma unroll
  for (int t = 0; t < 5; t++) { ev[t] = (ev[t] > -3.0e38f) ? expf(ev[t] - m) : 0.f; sum += ev[t]; }
  #pragma unroll
  for (int s = 16; s; s >>= 1) sum += __shfl_xor_sync(0xffffffffu, sum, s);
  float inv = 1.0f / sum;
  float* aT = g_alphaT + b*NM*NM + j*NM;
  #pragma unroll
  for (int t = 0; t < 5; t++) {
    int i = lane + 32*t;
    if (i < NM) aT[i] = ev[t] * inv;
  }
}

// ---------------- K4: agg_cg[j,l] = relu(sum_i alphaT[j,i]*xl[i,l]+bias) ----
__global__ void k4_aggcg(const float* __restrict__ gat_bias) {
  __shared__ __align__(16) float ATs[32][34];   // [i_inner][j_row]
  __shared__ __align__(16) float Xs[32][34];    // [i_inner][l_col]
  int b = blockIdx.z;
  int j0 = blockIdx.x * 32, l0 = blockIdx.y * 32;
  int tid = threadIdx.x, ty = tid >> 4, tx = tid & 15;
  const float* aT = g_alphaT + b*NM*NM;
  const float* xl = g_xl_cg + b*NM*NL;
  float a00 = 0.f, a01 = 0.f, a10 = 0.f, a11 = 0.f;
  for (int i0 = 0; i0 < NM; i0 += 32) {
    for (int idx = tid; idx < 1024; idx += 256) {
      int r = idx >> 5, c = idx & 31;
      ATs[c][r] = (j0 + r < NM && i0 + c < NM) ? aT[(j0 + r)*NM + i0 + c] : 0.f;
      Xs[r][c]  = (i0 + r < NM) ? xl[(i0 + r)*NL + l0 + c] : 0.f;
    }
    __syncthreads();
    #pragma unroll
    for (int k = 0; k < 32; k++) {
      float2 aj = *(const float2*)&ATs[k][2*ty];
      float2 x  = *(const float2*)&Xs[k][2*tx];
      a00 = fmaf(aj.x, x.x, a00); a01 = fmaf(aj.x, x.y, a01);
      a10 = fmaf(aj.y, x.x, a10); a11 = fmaf(aj.y, x.y, a11);
    }
    __syncthreads();
  }
  float* outp = g_agg_cg + b*NM*NL;
  int j = j0 + 2*ty, l = l0 + 2*tx;
  float bb0 = gat_bias[l], bb1 = gat_bias[l+1];
  if (j < NM)     { outp[j*NL + l] = fmaxf(a00 + bb0, 0.f);     outp[j*NL + l + 1] = fmaxf(a01 + bb1, 0.f); }
  if (j + 1 < NM) { outp[(j+1)*NL + l] = fmaxf(a10 + bb0, 0.f); outp[(j+1)*NL + l + 1] = fmaxf(a11 + bb1, 0.f); }
}

// ---------------- K6: output projection (290 x 800) @ (800 x 64) ------------
__global__ void k6_proj(const float* __restrict__ out_w,
                        const float* __restrict__ out_b) {
  __shared__ __align__(16) float As2[32][34];   // [k][row]
  __shared__ __align__(16) float Ws[32][34];    // [k][col]
  int g = blockIdx.z;
  const float* A = g ? g_agg_id : g_agg_cg;
  float* Y = g ? g_y_id : g_y_cg;
  int r0 = blockIdx.x * 32, c0 = blockIdx.y * 32;
  int tid = threadIdx.x, ty = tid >> 4, tx = tid & 15;
  float a00 = 0.f, a01 = 0.f, a10 = 0.f, a11 = 0.f;
  for (int k0 = 0; k0 < NL; k0 += 32) {
    for (int idx = tid; idx < 1024; idx += 256) {
      int r = idx >> 5, c = idx & 31;
      As2[c][r] = (r0 + r < NB*NM) ? A[(r0 + r)*NL + k0 + c] : 0.f;
      Ws[r][c]  = out_w[(k0 + r)*NC + c0 + c];
    }
    __syncthreads();
    #pragma unroll
    for (int k = 0; k < 32; k++) {
      float2 ar = *(const float2*)&As2[k][2*ty];
      float2 w  = *(const float2*)&Ws[k][2*tx];
      a00 = fmaf(ar.x, w.x, a00); a01 = fmaf(ar.x, w.y, a01);
      a10 = fmaf(ar.y, w.x, a10); a11 = fmaf(ar.y, w.y, a11);
    }
    __syncthreads();
  }
  int r = r0 + 2*ty, c = c0 + 2*tx;
  if (r < NB*NM)     { Y[r*NC + c] = a00 + out_b[c];     Y[r*NC + c + 1] = a01 + out_b[c+1]; }
  if (r + 1 < NB*NM) { Y[(r+1)*NC + c] = a10 + out_b[c]; Y[(r+1)*NC + c + 1] = a11 + out_b[c+1]; }
}

// ---------------- K7: write latent_y + loss2, last block finalizes ----------
__global__ void k7_final(const float* __restrict__ latent, float* __restrict__ d_out) {
  __shared__ float red[256];
  int tid = threadIdx.x;
  int idx = blockIdx.x * 256 + tid;
  float lp = 0.f;
  if (idx < NB*NN*NC) {
    int b = idx / (NC*NN), r = idx % (NC*NN);
    int c = r / NN, n = r % NN;
    d_out[idx] = g_y_cg[(b*NM + n)*NC + c];
    float d = latent[idx] - g_y_id[(b*NM + n)*NC + c];
    lp = d * d;
  }
  red[tid] = lp; __syncthreads();
  for (int s = 128; s; s >>= 1) { if (tid < s) red[tid] += red[tid + s]; __syncthreads(); }
  if (tid == 0) {
    atomicAdd(&g_loss2, red[0]);
    __threadfence();
    unsigned int old = atomicAdd(&g_cnt7, 1u);
    if (old == gridDim.x - 1) {
      float L2 = atomicAdd(&g_loss2, 0.f);
      d_out[NB*NN*NC] = g_loss1 / (float)(NB*NN*NN) + L2 / (float)(NB*NN*NC);
    }
  }
}

// ---------------- launch ----------------------------------------------------
extern "C" void kernel_launch(void* const* d_in, const int* in_sizes, int n_in,
                              void* d_out, int out_size) {
  (void)in_sizes; (void)n_in; (void)out_size;
  const float* latent    = (const float*)d_in[0];
  const float* a_dense_b = (const float*)d_in[2];
  const float* disc_w1   = (const float*)d_in[3];
  const float* disc_b1   = (const float*)d_in[4];
  const float* disc_w2   = (const float*)d_in[5];
  const float* disc_b2   = (const float*)d_in[6];
  const float* gat_wl    = (const float*)d_in[7];
  const float* gat_bl    = (const float*)d_in[8];
  const float* gat_wr    = (const float*)d_in[9];
  const float* gat_br    = (const float*)d_in[10];
  const float* gat_att   = (const float*)d_in[11];
  const float* gat_bias  = (const float*)d_in[12];
  const float* out_w     = (const float*)d_in[13];
  const float* out_b     = (const float*)d_in[14];
  float* out = (float*)d_out;

  uint32_t kg0, kg1, n10, n11, n20, n21, a, b;
  tf2x32(0u, 42u, 0u, 0u, a, b); kg0 = a; kg1 = b;
  tf2x32(0u, 42u, 0u, 1u, a, b); n10 = a; n11 = b;
  tf2x32(0u, 42u, 0u, 2u, a, b); n20 = a; n21 = b;

  int k0_threads = NB*NN*NC + NL + 2*NB*NM*NC + NB*NM*NM + 2*NB*NN + 2*NB*NM;
  k0_prep<<<(k0_threads + 255)/256, 256>>>(latent, a_dense_b, disc_w1, disc_b1,
                                           n10, n11, n20, n21);
  k1_gemm64<<<dim3(10, 25, 6), 256>>>(disc_w1, gat_wl, gat_wr, gat_bl, gat_br,
                                      disc_w2, gat_att);
  k235_mega<<<500 + NB*NM, 256>>>(disc_w2, gat_att, gat_bias);
  k2b_decide<<<162, 256>>>(disc_b2, kg0, kg1);
  k35_softmax<<<37, 256>>>();
  k4_aggcg<<<dim3(5, 25, 2), 256>>>(gat_bias);
  k6_proj<<<dim3(10, 2, 2), 256>>>(out_w, out_b);
  k7_final<<<72, 256>>>(latent, out);
}